// round 4
// baseline (speedup 1.0000x reference)
#include <cuda_runtime.h>

// RRGraphConv: out = (feat + segment_sum(feat[src], dst)) @ W.T + b
// (radius is dead input: torch.ones_like zeroes the power-law weight)

#define D_IN  64
#define D_OUT 128
#define MAX_NODES 100000
#define ROWS_PER_BLOCK 64

// Scratch mailbox (allocation-free per harness rules): h[node][k]
__device__ float g_h[(size_t)MAX_NODES * D_IN];

// packed f32x2 FMA: d = a * b + c elementwise on two packed floats
#define FMA_F32X2(d, a, b, c) \
    asm("fma.rn.f32x2 %0, %1, %2, %3;" : "=l"(d) : "l"(a), "l"(b), "l"(c))

// K0: zero the mailbox (write-only; "+feat" is folded into K2 staging)
__global__ void zero_h_kernel(int n4) {
    int i = blockIdx.x * blockDim.x + threadIdx.x;
    if (i < n4)
        reinterpret_cast<float4*>(g_h)[i] = make_float4(0.f, 0.f, 0.f, 0.f);
}

// K1: g_h[dst] += feat[src].
// 4 threads per edge; each thread: 4 gather LDG.128 (MLP=4) + 4 red.global.add.v4.f32.
__global__ void scatter_kernel(const float* __restrict__ feat,
                               const int*   __restrict__ src,
                               const int*   __restrict__ dst,
                               int E) {
    unsigned idx = blockIdx.x * blockDim.x + threadIdx.x;
    unsigned e = idx >> 2;
    if (e >= (unsigned)E) return;
    int c = (idx & 3) * 4;  // chunks c..c+3 of 16 float4 chunks per row

    int s = __ldg(&src[e]);
    int d = __ldg(&dst[e]);

    const float4* srow = reinterpret_cast<const float4*>(feat + (size_t)s * D_IN);
    float4 v0 = __ldg(srow + c);
    float4 v1 = __ldg(srow + c + 1);
    float4 v2 = __ldg(srow + c + 2);
    float4 v3 = __ldg(srow + c + 3);

    float* p = g_h + (size_t)d * D_IN + (size_t)c * 4;
    asm volatile("red.global.add.v4.f32 [%0], {%1, %2, %3, %4};"
                 :: "l"(p),      "f"(v0.x), "f"(v0.y), "f"(v0.z), "f"(v0.w) : "memory");
    asm volatile("red.global.add.v4.f32 [%0], {%1, %2, %3, %4};"
                 :: "l"(p + 4),  "f"(v1.x), "f"(v1.y), "f"(v1.z), "f"(v1.w) : "memory");
    asm volatile("red.global.add.v4.f32 [%0], {%1, %2, %3, %4};"
                 :: "l"(p + 8),  "f"(v2.x), "f"(v2.y), "f"(v2.z), "f"(v2.w) : "memory");
    asm volatile("red.global.add.v4.f32 [%0], {%1, %2, %3, %4};"
                 :: "l"(p + 12), "f"(v3.x), "f"(v3.y), "f"(v3.z), "f"(v3.w) : "memory");
}

// K2: out[row, j] = dot(feat[row,:] + g_h[row,:], W[j,:]) + b[j]
// thread j owns column j. Rows processed in PAIRS packed into f32x2 lanes:
//   acc = (acc_row_r, acc_row_r+1), W duplicated into packed 64-bit regs once.
// Rows staged interleaved in smem (sx[p][2k+rr]) so LDS.128 yields 2 packed
// pairs -> inner loop is 32 LDS.128 + 64 FFMA2 per row-pair (vs 128 FFMA).
__global__ __launch_bounds__(128)
void gemm_kernel(const float* __restrict__ feat,
                 const float* __restrict__ W,
                 const float* __restrict__ b,
                 float* __restrict__ out,
                 int N) {
    __shared__ __align__(16) float sx[2][2 * D_IN];  // [pair][2k + row_in_pair]
    const int j = threadIdx.x;                        // output column

    // W[j,k] duplicated into packed f32x2 regs: ww[k] = (w, w)
    unsigned long long ww[D_IN];
#pragma unroll
    for (int k = 0; k < D_IN; k++) {
        float wv = __ldg(&W[(size_t)j * D_IN + k]);
        asm("mov.b64 %0, {%1, %2};" : "=l"(ww[k]) : "f"(wv), "f"(wv));
    }
    const float bias = __ldg(&b[j]);

    const int row0 = blockIdx.x * ROWS_PER_BLOCK;

    for (int r = 0; r < ROWS_PER_BLOCK; r += 4) {
        const int row = row0 + r;
        if (row >= N) break;

        __syncthreads();
        // stage 4 rows (2 pairs): thread j -> pair p = j>>6, k = j&63
        {
            int p = j >> 6;
            int k = j & 63;
            int r0 = row + 2 * p, r1 = r0 + 1;
            float v0 = 0.f, v1 = 0.f;
            if (r0 < N) v0 = feat[(size_t)r0 * D_IN + k] + g_h[(size_t)r0 * D_IN + k];
            if (r1 < N) v1 = feat[(size_t)r1 * D_IN + k] + g_h[(size_t)r1 * D_IN + k];
            *reinterpret_cast<float2*>(&sx[p][2 * k]) = make_float2(v0, v1);
        }
        __syncthreads();

#pragma unroll
        for (int p = 0; p < 2; p++) {
            const int ro = row + 2 * p;
            if (ro >= N) break;

            unsigned long long acc0 = 0ull, acc1 = 0ull, acc2 = 0ull, acc3 = 0ull;
            const ulonglong2* xp = reinterpret_cast<const ulonglong2*>(sx[p]);
#pragma unroll
            for (int i = 0; i < D_IN / 2; i += 2) {
                ulonglong2 x0 = xp[i];      // pairs for k=2i, 2i+1 (LDS.128 bcast)
                ulonglong2 x1 = xp[i + 1];  // pairs for k=2i+2, 2i+3
                FMA_F32X2(acc0, ww[2 * i + 0], x0.x, acc0);
                FMA_F32X2(acc1, ww[2 * i + 1], x0.y, acc1);
                FMA_F32X2(acc2, ww[2 * i + 2], x1.x, acc2);
                FMA_F32X2(acc3, ww[2 * i + 3], x1.y, acc3);
            }
            float a0l, a0h, a1l, a1h, a2l, a2h, a3l, a3h;
            asm("mov.b64 {%0, %1}, %2;" : "=f"(a0l), "=f"(a0h) : "l"(acc0));
            asm("mov.b64 {%0, %1}, %2;" : "=f"(a1l), "=f"(a1h) : "l"(acc1));
            asm("mov.b64 {%0, %1}, %2;" : "=f"(a2l), "=f"(a2h) : "l"(acc2));
            asm("mov.b64 {%0, %1}, %2;" : "=f"(a3l), "=f"(a3h) : "l"(acc3));

            out[(size_t)ro * D_OUT + j] = (a0l + a1l) + (a2l + a3l) + bias;
            if (ro + 1 < N)
                out[(size_t)(ro + 1) * D_OUT + j] = (a0h + a1h) + (a2h + a3h) + bias;
        }
    }
}

extern "C" void kernel_launch(void* const* d_in, const int* in_sizes, int n_in,
                              void* d_out, int out_size) {
    const float* feat = (const float*)d_in[0];
    // d_in[1] = radius (unused: weight is ones_like'd away)
    const int*   src  = (const int*)d_in[2];
    const int*   dst  = (const int*)d_in[3];
    const float* W    = (const float*)d_in[4];
    const float* b    = (const float*)d_in[5];
    float* out = (float*)d_out;

    const int N = in_sizes[0] / D_IN;   // 100000
    const int E = in_sizes[2];          // 1600000

    // K0: g_h = 0
    {
        int n4 = (N * D_IN) / 4;
        int threads = 256;
        int blocks = (n4 + threads - 1) / threads;
        zero_h_kernel<<<blocks, threads>>>(n4);
    }

    // K1: g_h[dst] += feat[src]
    {
        long long total = (long long)E * 4;
        int threads = 256;
        int blocks = (int)((total + threads - 1) / threads);
        scatter_kernel<<<blocks, threads>>>(feat, src, dst, E);
    }

    // K2: out = (feat + g_h) @ W.T + b
    {
        int blocks = (N + ROWS_PER_BLOCK - 1) / ROWS_PER_BLOCK;
        gemm_kernel<<<blocks, 128>>>(feat, W, b, out, N);
    }
}